// round 2
// baseline (speedup 1.0000x reference)
#include <cuda_runtime.h>
#include <cuda_bf16.h>
#include <cstdint>

// ForceGrid: NGP deposit of 10M weighted particles into a 256^3 float grid.
// grid spans [-10,10]^3, n=256 per axis, dx = RN(20/255).
// XLA rewrites the reference's division by dx into multiplication by
// RN(1/dx_f32) == 12.75f exactly; we replicate that op sequence bit-for-bit
// with non-contractible intrinsics: fi5 = RN(RN(RN(x+10) * 12.75) + 0.5),
// index = trunc(fi5), in-bounds -> atomicAdd.

#define GRID_N 256

__device__ __forceinline__ void deposit_one(float x, float y, float z, float w,
                                            float* __restrict__ grid) {
    const float R = 12.75f;  // RN(1 / RN(20/255)) == 12.75 exactly (0.473 ulp below -> rounds up)
    // Three separately-rounded ops per axis, matching XLA's sub -> mul -> add HLOs.
    // Intrinsics prevent FMA contraction.
    float fx = __fadd_rn(__fmul_rn(__fadd_rn(x, 10.0f), R), 0.5f);
    float fy = __fadd_rn(__fmul_rn(__fadd_rn(y, 10.0f), R), 0.5f);
    float fz = __fadd_rn(__fmul_rn(__fadd_rn(z, 10.0f), R), 0.5f);
    int ix = (int)fx;   // trunc toward zero == astype(int32)
    int iy = (int)fy;
    int iz = (int)fz;
    // (unsigned) compare: negative -> huge -> fails. Values in (-1,0) truncate
    // to 0 and PASS, matching the reference's trunc-then-bounds-check.
    if (((unsigned)ix < GRID_N) & ((unsigned)iy < GRID_N) & ((unsigned)iz < GRID_N)) {
        int flat = (ix * GRID_N + iy) * GRID_N + iz;
        atomicAdd(grid + flat, w);   // no return use -> REDG
    }
}

__global__ void __launch_bounds__(256)
forcegrid_deposit_kernel(const float4* __restrict__ pos4,
                         const float4* __restrict__ w4,
                         const float*  __restrict__ pos_scalar,
                         const float*  __restrict__ w_scalar,
                         float* __restrict__ grid,
                         int n_particles) {
    int t = blockIdx.x * blockDim.x + threadIdx.x;
    int nquads_full = n_particles >> 2;           // quads with all 4 particles valid

    if (t < nquads_full) {
        // 3 coalesced float4 loads cover 4 particles' xyz; 1 float4 covers 4 weights
        float4 a = pos4[3 * t + 0];
        float4 b = pos4[3 * t + 1];
        float4 c = pos4[3 * t + 2];
        float4 w = w4[t];
        deposit_one(a.x, a.y, a.z, w.x, grid);
        deposit_one(a.w, b.x, b.y, w.y, grid);
        deposit_one(b.z, b.w, c.x, w.z, grid);
        deposit_one(c.y, c.z, c.w, w.w, grid);
    } else if (t == nquads_full) {
        // tail (n_particles % 4 != 0) — scalar path
        for (int p = nquads_full * 4; p < n_particles; p++) {
            deposit_one(pos_scalar[3 * p + 0], pos_scalar[3 * p + 1],
                        pos_scalar[3 * p + 2], w_scalar[p], grid);
        }
    }
}

extern "C" void kernel_launch(void* const* d_in, const int* in_sizes, int n_in,
                              void* d_out, int out_size) {
    const float* positions = (const float*)d_in[0];   // [N,3] f32
    const float* weights   = (const float*)d_in[1];   // [N]   f32
    float* grid = (float*)d_out;                      // 256^3 f32

    int n_particles = in_sizes[1];                    // N from weights

    // Output is poisoned; zero it first (graph-capturable async memset).
    cudaMemsetAsync(d_out, 0, (size_t)out_size * sizeof(float), 0);

    int nquads = (n_particles + 3) / 4;
    int threads = 256;
    int blocks = (nquads + 1 + threads - 1) / threads;  // +1 thread slot for tail
    forcegrid_deposit_kernel<<<blocks, threads, 0, 0>>>(
        (const float4*)positions, (const float4*)weights,
        positions, weights, grid, n_particles);
}

// round 3
// speedup vs baseline: 1.0706x; 1.0706x over previous
#include <cuda_runtime.h>
#include <cuda_bf16.h>
#include <cstdint>

// ForceGrid: NGP deposit of 10M weighted particles into a 256^3 float grid.
// fi5 = RN(RN(RN(x+10) * 12.75f) + 0.5f)  (replicates XLA's reciprocal-mul,
// three separately-rounded ops), index = trunc(fi5), in-bounds -> REDG.
// R3: __ldcs streaming loads (keep grid resident in L2) + 8 particles/thread
// (8 front-batched LDG.128 -> 2x MLP).

#define GRID_N 256

__device__ __forceinline__ void deposit_one(float x, float y, float z, float w,
                                            float* __restrict__ grid) {
    const float R = 12.75f;  // RN(1 / RN(20/255)) == 12.75 exactly
    float fx = __fadd_rn(__fmul_rn(__fadd_rn(x, 10.0f), R), 0.5f);
    float fy = __fadd_rn(__fmul_rn(__fadd_rn(y, 10.0f), R), 0.5f);
    float fz = __fadd_rn(__fmul_rn(__fadd_rn(z, 10.0f), R), 0.5f);
    int ix = (int)fx;   // trunc toward zero == astype(int32)
    int iy = (int)fy;
    int iz = (int)fz;
    if (((unsigned)ix < GRID_N) & ((unsigned)iy < GRID_N) & ((unsigned)iz < GRID_N)) {
        int flat = (ix * GRID_N + iy) * GRID_N + iz;
        atomicAdd(grid + flat, w);   // no return use -> REDG
    }
}

__global__ void __launch_bounds__(256)
forcegrid_deposit_kernel(const float4* __restrict__ pos4,
                         const float4* __restrict__ w4,
                         const float*  __restrict__ pos_scalar,
                         const float*  __restrict__ w_scalar,
                         float* __restrict__ grid,
                         int n_particles) {
    int t = blockIdx.x * blockDim.x + threadIdx.x;
    int noct_full = n_particles >> 3;   // groups of 8 fully-valid particles

    if (t < noct_full) {
        // 8 particles: 6 coalesced float4 position loads + 2 float4 weight loads,
        // all front-batched (MLP=8), streaming (evict-first) so the 64MB grid
        // keeps L2 residency for the atomics.
        float4 a = __ldcs(&pos4[6 * t + 0]);
        float4 b = __ldcs(&pos4[6 * t + 1]);
        float4 c = __ldcs(&pos4[6 * t + 2]);
        float4 d = __ldcs(&pos4[6 * t + 3]);
        float4 e = __ldcs(&pos4[6 * t + 4]);
        float4 f = __ldcs(&pos4[6 * t + 5]);
        float4 w0 = __ldcs(&w4[2 * t + 0]);
        float4 w1 = __ldcs(&w4[2 * t + 1]);

        deposit_one(a.x, a.y, a.z, w0.x, grid);
        deposit_one(a.w, b.x, b.y, w0.y, grid);
        deposit_one(b.z, b.w, c.x, w0.z, grid);
        deposit_one(c.y, c.z, c.w, w0.w, grid);
        deposit_one(d.x, d.y, d.z, w1.x, grid);
        deposit_one(d.w, e.x, e.y, w1.y, grid);
        deposit_one(e.z, e.w, f.x, w1.z, grid);
        deposit_one(f.y, f.z, f.w, w1.w, grid);
    } else if (t == noct_full) {
        // tail (n_particles % 8 != 0) — scalar path
        for (int p = noct_full * 8; p < n_particles; p++) {
            deposit_one(__ldcs(&pos_scalar[3 * p + 0]),
                        __ldcs(&pos_scalar[3 * p + 1]),
                        __ldcs(&pos_scalar[3 * p + 2]),
                        __ldcs(&w_scalar[p]), grid);
        }
    }
}

extern "C" void kernel_launch(void* const* d_in, const int* in_sizes, int n_in,
                              void* d_out, int out_size) {
    const float* positions = (const float*)d_in[0];   // [N,3] f32
    const float* weights   = (const float*)d_in[1];   // [N]   f32
    float* grid = (float*)d_out;                      // 256^3 f32

    int n_particles = in_sizes[1];                    // N from weights

    // Output is poisoned; zero it first (graph-capturable async memset).
    cudaMemsetAsync(d_out, 0, (size_t)out_size * sizeof(float), 0);

    int nocts = (n_particles + 7) / 8;
    int threads = 256;
    int blocks = (nocts + 1 + threads - 1) / threads;  // +1 slot for tail thread
    forcegrid_deposit_kernel<<<blocks, threads, 0, 0>>>(
        (const float4*)positions, (const float4*)weights,
        positions, weights, grid, n_particles);
}

// round 4
// speedup vs baseline: 1.0754x; 1.0045x over previous
#include <cuda_runtime.h>
#include <cuda_bf16.h>
#include <cstdint>

// ForceGrid: NGP deposit of 10M weighted particles into a 256^3 float grid.
// fi5 = RN(RN(RN(x+10) * 12.75f) + 0.5f)  (replicates XLA's reciprocal-mul,
// three separately-rounded ops), index = trunc(fi5), in-bounds -> REDG.
// R4: persistent grid-stride + register double-buffer — next iteration's
// coalesced loads are in flight while the current iteration's atomics issue,
// keeping the REDG dispatch pipe (the bottleneck) continuously fed.

#define GRID_N 256

__device__ __forceinline__ void deposit_one(float x, float y, float z, float w,
                                            float* __restrict__ grid) {
    const float R = 12.75f;  // RN(1 / RN(20/255)) == 12.75 exactly
    float fx = __fadd_rn(__fmul_rn(__fadd_rn(x, 10.0f), R), 0.5f);
    float fy = __fadd_rn(__fmul_rn(__fadd_rn(y, 10.0f), R), 0.5f);
    float fz = __fadd_rn(__fmul_rn(__fadd_rn(z, 10.0f), R), 0.5f);
    int ix = (int)fx;   // trunc toward zero == astype(int32)
    int iy = (int)fy;
    int iz = (int)fz;
    if (((unsigned)ix < GRID_N) & ((unsigned)iy < GRID_N) & ((unsigned)iz < GRID_N)) {
        int flat = (ix * GRID_N + iy) * GRID_N + iz;
        atomicAdd(grid + flat, w);   // no return use -> REDG
    }
}

__global__ void __launch_bounds__(256)
forcegrid_deposit_kernel(const float4* __restrict__ pos4,
                         const float4* __restrict__ w4,
                         const float*  __restrict__ pos_scalar,
                         const float*  __restrict__ w_scalar,
                         float* __restrict__ grid,
                         int n_particles) {
    const int nq = n_particles >> 2;                 // full quads
    const int stride = gridDim.x * blockDim.x;
    int q = blockIdx.x * blockDim.x + threadIdx.x;

    // Software pipeline: cur regs hold quad q, next loads issue before deposits.
    float4 a, b, c, w;
    bool have = (q < nq);
    if (have) {
        a = __ldcs(&pos4[3 * q + 0]);
        b = __ldcs(&pos4[3 * q + 1]);
        c = __ldcs(&pos4[3 * q + 2]);
        w = __ldcs(&w4[q]);
    }
    while (have) {
        const int qn = q + stride;
        const bool haven = (qn < nq);
        float4 an, bn, cn, wn;
        if (haven) {                                  // prefetch next quad
            an = __ldcs(&pos4[3 * qn + 0]);
            bn = __ldcs(&pos4[3 * qn + 1]);
            cn = __ldcs(&pos4[3 * qn + 2]);
            wn = __ldcs(&w4[qn]);
        }
        // deposit current quad while next loads are in flight
        deposit_one(a.x, a.y, a.z, w.x, grid);
        deposit_one(a.w, b.x, b.y, w.y, grid);
        deposit_one(b.z, b.w, c.x, w.z, grid);
        deposit_one(c.y, c.z, c.w, w.w, grid);
        a = an; b = bn; c = cn; w = wn;               // rotate buffers
        q = qn; have = haven;
    }

    // tail (n_particles % 4 != 0) — single thread, scalar path
    if (blockIdx.x == 0 && threadIdx.x == 0) {
        for (int p = nq * 4; p < n_particles; p++) {
            deposit_one(pos_scalar[3 * p + 0], pos_scalar[3 * p + 1],
                        pos_scalar[3 * p + 2], w_scalar[p], grid);
        }
    }
}

extern "C" void kernel_launch(void* const* d_in, const int* in_sizes, int n_in,
                              void* d_out, int out_size) {
    const float* positions = (const float*)d_in[0];   // [N,3] f32
    const float* weights   = (const float*)d_in[1];   // [N]   f32
    float* grid = (float*)d_out;                      // 256^3 f32

    int n_particles = in_sizes[1];                    // N from weights

    // Output is poisoned; zero it first (graph-capturable async memset).
    cudaMemsetAsync(d_out, 0, (size_t)out_size * sizeof(float), 0);

    // Persistent-ish launch: ~8 resident blocks/SM worth of work slots;
    // grid-stride loop makes the exact count non-critical.
    int threads = 256;
    int blocks = 148 * 8;   // 1184 blocks -> ~303k threads, ~8 quads/thread
    forcegrid_deposit_kernel<<<blocks, threads, 0, 0>>>(
        (const float4*)positions, (const float4*)weights,
        positions, weights, grid, n_particles);
}

// round 6
// speedup vs baseline: 1.2792x; 1.1895x over previous
#include <cuda_runtime.h>
#include <cuda_bf16.h>
#include <cstdint>

// ForceGrid: NGP deposit of 10M weighted particles into a 256^3 float grid.
// fi5 = RN(RN(RN(x+10) * 12.75f) + 0.5f)  (replicates XLA's reciprocal-mul,
// three separately-rounded ops), index = trunc(fi5), in-bounds -> red.add.
// R6: pin the 64MB grid in L2 with evict_last policy (cache_hint form on both
// the zero stores and the reductions) so random 32B sector fetches stay in L2.

#define GRID_N 256

__device__ __forceinline__ uint64_t make_evict_last_policy() {
    uint64_t pol;
    asm volatile("createpolicy.fractional.L2::evict_last.b64 %0, 1.0;" : "=l"(pol));
    return pol;
}

__device__ __forceinline__ void deposit_one(float x, float y, float z, float w,
                                            float* __restrict__ grid,
                                            uint64_t pol) {
    const float R = 12.75f;  // RN(1 / RN(20/255)) == 12.75 exactly
    float fx = __fadd_rn(__fmul_rn(__fadd_rn(x, 10.0f), R), 0.5f);
    float fy = __fadd_rn(__fmul_rn(__fadd_rn(y, 10.0f), R), 0.5f);
    float fz = __fadd_rn(__fmul_rn(__fadd_rn(z, 10.0f), R), 0.5f);
    int ix = (int)fx;   // trunc toward zero == astype(int32)
    int iy = (int)fy;
    int iz = (int)fz;
    if (((unsigned)ix < GRID_N) & ((unsigned)iy < GRID_N) & ((unsigned)iz < GRID_N)) {
        int flat = (ix * GRID_N + iy) * GRID_N + iz;
        // Reduction with L2 evict_last cache hint: keeps grid lines resident.
        asm volatile("red.global.L2::cache_hint.add.f32 [%0], %1, %2;"
                     :: "l"(grid + flat), "f"(w), "l"(pol) : "memory");
    }
}

// Zero the grid with evict_last-policy stores: lines enter L2 dirty + pinned.
__global__ void __launch_bounds__(256)
forcegrid_zero_kernel(float4* __restrict__ grid4, int n4) {
    int i = blockIdx.x * blockDim.x + threadIdx.x;
    int stride = gridDim.x * blockDim.x;
    const float z = 0.0f;
    const uint64_t pol = make_evict_last_policy();
    for (; i < n4; i += stride) {
        asm volatile("st.global.L2::cache_hint.v4.f32 [%0], {%1, %2, %3, %4}, %5;"
                     :: "l"(grid4 + i), "f"(z), "f"(z), "f"(z), "f"(z), "l"(pol)
                     : "memory");
    }
}

__global__ void __launch_bounds__(256)
forcegrid_deposit_kernel(const float4* __restrict__ pos4,
                         const float4* __restrict__ w4,
                         const float*  __restrict__ pos_scalar,
                         const float*  __restrict__ w_scalar,
                         float* __restrict__ grid,
                         int n_particles) {
    const int nq = n_particles >> 2;                 // full quads
    const int stride = gridDim.x * blockDim.x;
    int q = blockIdx.x * blockDim.x + threadIdx.x;
    const uint64_t pol = make_evict_last_policy();

    // Software pipeline: cur regs hold quad q, next loads issue before deposits.
    float4 a, b, c, w;
    bool have = (q < nq);
    if (have) {
        a = __ldcs(&pos4[3 * q + 0]);
        b = __ldcs(&pos4[3 * q + 1]);
        c = __ldcs(&pos4[3 * q + 2]);
        w = __ldcs(&w4[q]);
    }
    while (have) {
        const int qn = q + stride;
        const bool haven = (qn < nq);
        float4 an, bn, cn, wn;
        if (haven) {                                  // prefetch next quad
            an = __ldcs(&pos4[3 * qn + 0]);
            bn = __ldcs(&pos4[3 * qn + 1]);
            cn = __ldcs(&pos4[3 * qn + 2]);
            wn = __ldcs(&w4[qn]);
        }
        deposit_one(a.x, a.y, a.z, w.x, grid, pol);
        deposit_one(a.w, b.x, b.y, w.y, grid, pol);
        deposit_one(b.z, b.w, c.x, w.z, grid, pol);
        deposit_one(c.y, c.z, c.w, w.w, grid, pol);
        a = an; b = bn; c = cn; w = wn;               // rotate buffers
        q = qn; have = haven;
    }

    // tail (n_particles % 4 != 0) — single thread, scalar path
    if (blockIdx.x == 0 && threadIdx.x == 0) {
        for (int p = nq * 4; p < n_particles; p++) {
            deposit_one(pos_scalar[3 * p + 0], pos_scalar[3 * p + 1],
                        pos_scalar[3 * p + 2], w_scalar[p], grid, pol);
        }
    }
}

extern "C" void kernel_launch(void* const* d_in, const int* in_sizes, int n_in,
                              void* d_out, int out_size) {
    const float* positions = (const float*)d_in[0];   // [N,3] f32
    const float* weights   = (const float*)d_in[1];   // [N]   f32
    float* grid = (float*)d_out;                      // 256^3 f32

    int n_particles = in_sizes[1];                    // N from weights

    int threads = 256;

    // Zero + L2-pin the grid (out_size is 256^3, divisible by 4).
    int n4 = out_size / 4;
    int zblocks = 148 * 4;
    forcegrid_zero_kernel<<<zblocks, threads, 0, 0>>>((float4*)d_out, n4);

    // Persistent deposit with grid-stride double-buffer.
    int blocks = 148 * 8;
    forcegrid_deposit_kernel<<<blocks, threads, 0, 0>>>(
        (const float4*)positions, (const float4*)weights,
        positions, weights, grid, n_particles);
}